// round 3
// baseline (speedup 1.0000x reference)
#include <cuda_runtime.h>
#include <cstdint>

#define GRID  128
#define NTHR  256
#define BSZ   128
#define TE    512
#define HD    256
#define H2D   128
#define MELD  80
#define RF    5
#define STEPS 200
#define G3    768
#define SMEM_BYTES 66560   // max(GRU: 2*32*65*16 = 66560, linear K=512: 32*129*16 = 66048)

// ---------------- device scratch (allocation-free) ---------------------------------
__device__ float g_w1enc[(size_t)BSZ * TE * HD];        // 67 MB
__device__ float g_pre1[STEPS * BSZ * HD];
__device__ float g_xs[STEPS * BSZ * H2D];
__device__ float g_giatt[(size_t)STEPS * BSZ * G3];     // x@Wih^T + bih for att GRU, all steps
__device__ float g_dbuf[2][BSZ * HD];
__device__ float g_h1buf[2][BSZ * HD];
__device__ float g_h2buf[2][BSZ * HD];
__device__ float g_q[BSZ * HD];
__device__ float g_ddot[BSZ * HD];
__device__ float g_p[BSZ * HD];
__device__ float g_in2[BSZ * HD];
__device__ float g_s[BSZ * HD];
__device__ float g_sc[BSZ * TE];
__device__ unsigned g_bar_count;   // zero-initialized; barrier leaves it at 0
__device__ unsigned g_bar_epoch;   // monotonically increasing across launches

// ---------------- helpers ----------------------------------------------------------
__device__ __forceinline__ float tanh_fast(float x) {
    float y; asm("tanh.approx.f32 %0, %1;" : "=f"(y) : "f"(x)); return y;
}
__device__ __forceinline__ float sigmoidf_(float x) { return 1.f / (1.f + __expf(-x)); }
__device__ __forceinline__ unsigned ld_acq(const unsigned* p) {
    unsigned v; asm volatile("ld.acquire.gpu.b32 %0, [%1];" : "=r"(v) : "l"(p)); return v;
}

// Grid-wide barrier (all GRID blocks co-resident by construction).
__device__ __forceinline__ void gsync(unsigned target)
{
    __syncthreads();
    if (threadIdx.x == 0) {
        __threadfence();
        unsigned a = atomicAdd(&g_bar_count, 1u);
        if (a == GRID - 1u) {
            g_bar_count = 0u;          // safe: nobody arrives for next barrier until epoch bumps
            __threadfence();
            atomicAdd(&g_bar_epoch, 1u);
        } else {
            while ((int)(ld_acq(&g_bar_epoch) - target) < 0) __nanosleep(32);
        }
    }
    __syncthreads();
}

// ---------------- tiled linear: Y[r,j] = act(X[r,:] @ W[j,:] + bias[j]) ------------
// X = concat(X1 first k1_4*4 cols, X2 rest). If dec != null, row r gathers the
// teacher-forced mel frame: dec + (r&127)*1000*80 + (r>>7)*400.
// Tiles: nrowtiles x (ntilecols/cgs); per tile: 32 rows, cgs*16 cols.
__device__ void dev_linear(const float* __restrict__ X1, long ld1, int k1_4,
                           const float* __restrict__ X2, long ld2,
                           int nf4,
                           const float* __restrict__ W, const float* __restrict__ bias,
                           float* __restrict__ Y, long ldy, int relu,
                           int nrowtiles, int ntilecols, int cgs,
                           const float* __restrict__ dec,
                           float4* sm4)
{
    const int tid = threadIdx.x, lane = tid & 31, w = tid >> 5;
    const int stride4 = nf4 + 1;
    const int K = nf4 * 4;
    const int ctiles = ntilecols / cgs;
    const int tiles = nrowtiles * ctiles;
    for (int t = blockIdx.x; t < tiles; t += GRID) {
        const int rt = t / ctiles;
        const int cb = (t - rt * ctiles) * cgs;
        const long r0 = (long)rt * 32;
        for (int idx = tid; idx < 32 * nf4; idx += NTHR) {
            int row = idx / nf4, c4 = idx - row * nf4;
            long r = r0 + row;
            float4 v;
            if (dec) {
                const float* src = dec + (r & 127) * 80000L + (r >> 7) * (RF * MELD);
                v = *(const float4*)(src + (size_t)c4 * 4);
            } else if (c4 < k1_4) {
                v = *(const float4*)(X1 + r * ld1 + (size_t)c4 * 4);
            } else {
                v = *(const float4*)(X2 + r * ld2 + (size_t)(c4 - k1_4) * 4);
            }
            sm4[row * stride4 + c4] = v;
        }
        __syncthreads();
        const float4* xr = sm4 + lane * stride4;
        for (int cg = 0; cg < cgs; cg++) {
            const int j0 = (cb + cg) * 16 + w * 2;
            float acc0 = bias[j0], acc1 = bias[j0 + 1];
            const float4* W0 = (const float4*)(W + (size_t)j0 * K);
            const float4* W1 = W0 + nf4;
#pragma unroll 4
            for (int k = 0; k < nf4; k++) {
                float4 x = xr[k];
                float4 a = W0[k];
                acc0 += x.x * a.x + x.y * a.y + x.z * a.z + x.w * a.w;
                float4 b = W1[k];
                acc1 += x.x * b.x + x.y * b.y + x.z * b.z + x.w * b.w;
            }
            if (relu) { acc0 = fmaxf(acc0, 0.f); acc1 = fmaxf(acc1, 0.f); }
            Y[(r0 + lane) * ldy + j0]     = acc0;
            Y[(r0 + lane) * ldy + j0 + 1] = acc1;
        }
        __syncthreads();
    }
}

// ---------------- GRU step (128 tiles: jt 0..31 x rt 0..3) -------------------------
__device__ void dev_gru(const float* __restrict__ GIpre,
                        const float* __restrict__ X,
                        const float* __restrict__ Wih, const float* __restrict__ bih,
                        const float* __restrict__ Whh, const float* __restrict__ bhh,
                        const float* __restrict__ H, float* __restrict__ Hnew,
                        float* __restrict__ Sum, float4* sm4)
{
    const int tid = threadIdx.x, lane = tid & 31, w = tid >> 5;
    float4* Hs4 = sm4;
    float4* Xs4 = sm4 + 32 * 65;
    for (int t = blockIdx.x; t < 128; t += GRID) {
        const int jt = t & 31, rt = t >> 5;
        const int r0 = rt * 32;
        for (int idx = tid; idx < 32 * 64; idx += NTHR) {
            int row = idx >> 6, c4 = idx & 63;
            Hs4[row * 65 + c4] = *(const float4*)(H + (size_t)(r0 + row) * HD + (size_t)c4 * 4);
        }
        if (X) {
            for (int idx = tid; idx < 32 * 64; idx += NTHR) {
                int row = idx >> 6, c4 = idx & 63;
                Xs4[row * 65 + c4] = *(const float4*)(X + (size_t)(r0 + row) * HD + (size_t)c4 * 4);
            }
        }
        __syncthreads();
        const int j = jt * 8 + w;
        const int b = r0 + lane;

        float gir, giz, gin;
        if (GIpre) {
            const float* gp = GIpre + (size_t)b * G3;
            gir = gp[j]; giz = gp[j + HD]; gin = gp[j + 2 * HD];
        } else {
            float a0 = bih[j], a1 = bih[j + HD], a2 = bih[j + 2 * HD];
            const float4* Wr = (const float4*)(Wih + (size_t)j * HD);
            const float4* Wz = (const float4*)(Wih + (size_t)(j + HD) * HD);
            const float4* Wn = (const float4*)(Wih + (size_t)(j + 2 * HD) * HD);
            const float4* xr = Xs4 + lane * 65;
#pragma unroll 4
            for (int k = 0; k < 64; k++) {
                float4 x = xr[k];
                float4 p0 = Wr[k]; a0 += x.x * p0.x + x.y * p0.y + x.z * p0.z + x.w * p0.w;
                float4 p1 = Wz[k]; a1 += x.x * p1.x + x.y * p1.y + x.z * p1.z + x.w * p1.w;
                float4 p2 = Wn[k]; a2 += x.x * p2.x + x.y * p2.y + x.z * p2.z + x.w * p2.w;
            }
            gir = a0; giz = a1; gin = a2;
        }

        float b0 = bhh[j], b1 = bhh[j + HD], b2 = bhh[j + 2 * HD];
        {
            const float4* Vr = (const float4*)(Whh + (size_t)j * HD);
            const float4* Vz = (const float4*)(Whh + (size_t)(j + HD) * HD);
            const float4* Vn = (const float4*)(Whh + (size_t)(j + 2 * HD) * HD);
            const float4* hr = Hs4 + lane * 65;
#pragma unroll 4
            for (int k = 0; k < 64; k++) {
                float4 h = hr[k];
                float4 p0 = Vr[k]; b0 += h.x * p0.x + h.y * p0.y + h.z * p0.z + h.w * p0.w;
                float4 p1 = Vz[k]; b1 += h.x * p1.x + h.y * p1.y + h.z * p1.z + h.w * p1.w;
                float4 p2 = Vn[k]; b2 += h.x * p2.x + h.y * p2.y + h.z * p2.z + h.w * p2.w;
            }
        }
        float hv = ((const float*)Hs4)[lane * 260 + j];
        float rg = sigmoidf_(gir + b0);
        float zg = sigmoidf_(giz + b1);
        float ng = tanhf(gin + rg * b2);    // accurate tanh in the recurrence
        float hn = (1.f - zg) * ng + zg * hv;
        Hnew[(size_t)b * HD + j] = hn;
        if (Sum) Sum[(size_t)b * HD + j] = hn + ((const float*)Xs4)[lane * 260 + j];
        __syncthreads();
    }
}

// ---------------- attention scores: 512 units = b(128) x 4 t-chunks of 128 ---------
__device__ void dev_scores(const float* __restrict__ vw, const float* __restrict__ vb,
                           float* smf)
{
    const int tid = threadIdx.x, lane = tid & 31, w = tid >> 5;
    float* qs = smf;
    float* vs = smf + HD;
    const float vb0 = vb[0];
    for (int u = blockIdx.x; u < 512; u += GRID) {
        const int b = u >> 2, ch = u & 3;
        qs[tid] = g_q[(size_t)b * HD + tid];
        vs[tid] = vw[tid];
        __syncthreads();
        const float* wb = g_w1enc + (size_t)b * TE * HD + (size_t)ch * 128 * HD;
        for (int tt = w; tt < 128; tt += 8) {
            const float* row = wb + (size_t)tt * HD;
            float acc = 0.f;
#pragma unroll
            for (int m = 0; m < 8; m++) {
                int h = m * 32 + lane;
                acc += vs[h] * tanh_fast(row[h] + qs[h]);
            }
            for (int o = 16; o; o >>= 1) acc += __shfl_down_sync(0xffffffffu, acc, o);
            if (lane == 0) g_sc[b * TE + ch * 128 + tt] = acc + vb0;
        }
        __syncthreads();
    }
}

// ---------------- softmax + context: one block per batch row -----------------------
__device__ void dev_context(const float* __restrict__ enc, float* smf)
{
    const int tid = threadIdx.x, lane = tid & 31, w = tid >> 5;
    float* sc  = smf;        // 512
    float* red = smf + TE;   // 8
    for (int b = blockIdx.x; b < BSZ; b += GRID) {
        float s0 = g_sc[b * TE + tid], s1 = g_sc[b * TE + 256 + tid];
        float v = fmaxf(s0, s1);
        for (int o = 16; o; o >>= 1) v = fmaxf(v, __shfl_xor_sync(0xffffffffu, v, o));
        if (lane == 0) red[w] = v;
        __syncthreads();
        float mx = red[0];
#pragma unroll
        for (int k = 1; k < 8; k++) mx = fmaxf(mx, red[k]);
        float e0 = __expf(s0 - mx), e1 = __expf(s1 - mx);
        __syncthreads();                        // everyone done with red before reuse
        sc[tid] = e0; sc[tid + 256] = e1;
        float s = e0 + e1;
        for (int o = 16; o; o >>= 1) s += __shfl_xor_sync(0xffffffffu, s, o);
        if (lane == 0) red[w] = s;
        __syncthreads();
        float sum = red[0];
#pragma unroll
        for (int k = 1; k < 8; k++) sum += red[k];
        const float inv = 1.f / sum;

        const float* eb = enc + (size_t)b * TE * HD;
        float acc = 0.f;
#pragma unroll 8
        for (int t = 0; t < TE; t++) acc += sc[t] * eb[(size_t)t * HD + tid];
        g_ddot[(size_t)b * HD + tid] = acc * inv;
        __syncthreads();
    }
}

// ---------------- the persistent kernel --------------------------------------------
__global__ void __launch_bounds__(NTHR, 1)
mel_persist(const float* __restrict__ enc, const float* __restrict__ dec,
            const float* pre_w1, const float* pre_b1,
            const float* pre_w2, const float* pre_b2,
            const float* w1, const float* b1, const float* w2, const float* b2,
            const float* v_w, const float* v_b,
            const float* proj_w, const float* proj_b,
            const float* out_w, const float* out_b,
            const float* att_wih, const float* att_whh,
            const float* att_bih, const float* att_bhh,
            const float* g1_wih, const float* g1_whh,
            const float* g1_bih, const float* g1_bhh,
            const float* g2_wih, const float* g2_whh,
            const float* g2_bih, const float* g2_bhh,
            float* __restrict__ out)
{
    extern __shared__ float4 sm4[];
    float* smf = (float*)sm4;
    const unsigned base = ld_acq(&g_bar_epoch);   // uniform: read before any arrival
    unsigned ep = 0;
#define GS() gsync(base + (++ep))

    // P0: zero recurrent states (every launch; deterministic)
    for (int i = blockIdx.x * NTHR + threadIdx.x; i < BSZ * HD; i += GRID * NTHR) {
        g_dbuf[0][i] = 0.f;  g_dbuf[1][i] = 0.f;
        g_h1buf[0][i] = 0.f; g_h1buf[1][i] = 0.f;
        g_h2buf[0][i] = 0.f; g_h2buf[1][i] = 0.f;
    }
    // P1: pre-net L1 (gather from dec): [25600,80] -> [25600,256], relu
    dev_linear(nullptr, 0, 0, nullptr, 0, 20, pre_w1, pre_b1, g_pre1, HD, 1,
               800, 16, 16, dec, sm4);
    GS();
    // P2: pre-net L2 -> [25600,128], relu
    dev_linear(g_pre1, HD, 64, nullptr, 0, 64, pre_w2, pre_b2, g_xs, H2D, 1,
               800, 8, 8, nullptr, sm4);
    GS();
    // P3: att GRU input gates, all steps: [25600,128] -> [25600,768]
    dev_linear(g_xs, H2D, 32, nullptr, 0, 32, att_wih, att_bih, g_giatt, G3, 0,
               800, 48, 48, nullptr, sm4);
    GS();
    // P4: w1enc = enc @ w1^T + b1 : [65536,256]
    dev_linear(enc, HD, 64, nullptr, 0, 64, w1, b1, g_w1enc, HD, 0,
               2048, 16, 16, nullptr, sm4);
    GS();

    for (int i = 0; i < STEPS; i++) {
        const int cur = i & 1, prev = cur ^ 1;
        float* dprev = g_dbuf[prev]; float* dcur = g_dbuf[cur];

        // A: attention GRU (input gates precomputed)
        dev_gru(g_giatt + (size_t)i * BSZ * G3, nullptr,
                nullptr, nullptr, att_whh, att_bhh, dprev, dcur, nullptr, sm4);
        GS();
        // B: q = d @ w2^T + b2
        dev_linear(dcur, HD, 64, nullptr, 0, 64, w2, b2, g_q, HD, 0,
                   4, 16, 1, nullptr, sm4);
        GS();
        // C1: scores
        dev_scores(v_w, v_b, smf);
        GS();
        // C2+C3: softmax + context
        dev_context(enc, smf);
        GS();
        // D: p = [d | ddot] @ proj_w^T + proj_b
        dev_linear(dcur, HD, 64, g_ddot, HD, 128, proj_w, proj_b, g_p, HD, 0,
                   4, 16, 1, nullptr, sm4);
        GS();
        // E: GRU1; in2 = p + o1
        dev_gru(nullptr, g_p, g1_wih, g1_bih, g1_whh, g1_bhh,
                g_h1buf[prev], g_h1buf[cur], g_in2, sm4);
        GS();
        // F: GRU2; s = in2 + o2
        dev_gru(nullptr, g_in2, g2_wih, g2_bih, g2_whh, g2_bhh,
                g_h2buf[prev], g_h2buf[cur], g_s, sm4);
        GS();
        // G: out = s @ out_w^T + out_b (scatter rows into [bs,1000,80]).
        // No trailing barrier: next step's A touches only the d ping-pong buffer,
        // disjoint from everything G reads/writes; the A->B barrier covers G too.
        dev_linear(g_s, HD, 64, nullptr, 0, 64, out_w, out_b,
                   out + (size_t)i * RF * MELD, 1000L * MELD, 0,
                   4, 25, 1, nullptr, sm4);
    }
#undef GS
}

// ---------------- host launch: ONE graph node --------------------------------------
extern "C" void kernel_launch(void* const* d_in, const int* in_sizes, int n_in,
                              void* d_out, int out_size)
{
    cudaFuncSetAttribute(mel_persist, cudaFuncAttributeMaxDynamicSharedMemorySize,
                         SMEM_BYTES);
    mel_persist<<<GRID, NTHR, SMEM_BYTES>>>(
        (const float*)d_in[0],  (const float*)d_in[1],
        (const float*)d_in[2],  (const float*)d_in[3],
        (const float*)d_in[4],  (const float*)d_in[5],
        (const float*)d_in[6],  (const float*)d_in[7],
        (const float*)d_in[8],  (const float*)d_in[9],
        (const float*)d_in[10], (const float*)d_in[11],
        (const float*)d_in[12], (const float*)d_in[13],
        (const float*)d_in[14], (const float*)d_in[15],
        (const float*)d_in[16], (const float*)d_in[17],
        (const float*)d_in[18], (const float*)d_in[19],
        (const float*)d_in[20], (const float*)d_in[21],
        (const float*)d_in[22], (const float*)d_in[23],
        (const float*)d_in[24], (const float*)d_in[25],
        (const float*)d_in[26], (const float*)d_in[27],
        (float*)d_out);
}